// round 3
// baseline (speedup 1.0000x reference)
#include <cuda_runtime.h>
#include <math.h>

#define NNODES  50000
#define BATCH   2
#define DH      128
#define TOTROWS (BATCH * NNODES)
#define MAXE    800000

typedef unsigned long long ull;

// ---- device scratch (allocation-guard-safe) ----
__device__ float g_support[(size_t)TOTROWS * DH];
__device__ int   g_deg[NNODES];
__device__ int   g_off[NNODES + 1];
__device__ int   g_cursor[NNODES];
__device__ int   g_adj[MAXE];
__device__ float g_acc[32];
__device__ unsigned int g_done;

// ---- packed fp32x2 helpers (Blackwell dual-issue fp32) ----
__device__ __forceinline__ ull pack2(float a, float b) {
    ull r; asm("mov.b64 %0, {%1, %2};" : "=l"(r) : "f"(a), "f"(b)); return r;
}
__device__ __forceinline__ void unpack2(ull v, float& a, float& b) {
    asm("mov.b64 {%0, %1}, %2;" : "=f"(a), "=f"(b) : "l"(v));
}
__device__ __forceinline__ void ffma2(ull& d, ull a, ull b) {
    asm("fma.rn.f32x2 %0, %1, %2, %0;" : "+l"(d) : "l"(a), "l"(b));
}

__device__ __forceinline__ float gelu_exact(float v) {
    return 0.5f * v * (1.0f + erff(v * 0.70710678118654752f));
}

// ---------------------------------------------------------------------------
// K0: zero degree histogram + accumulators + completion ticket
// ---------------------------------------------------------------------------
__global__ void k_zero() {
    int i = blockIdx.x * blockDim.x + threadIdx.x;
    for (; i < NNODES; i += gridDim.x * blockDim.x) g_deg[i] = 0;
    if (blockIdx.x == 0 && threadIdx.x < 32) g_acc[threadIdx.x] = 0.f;
    if (blockIdx.x == 0 && threadIdx.x == 0) g_done = 0u;
}

// ---------------------------------------------------------------------------
// K1: histogram of dst
// ---------------------------------------------------------------------------
__global__ void k_hist(const int* __restrict__ ei, int nedges) {
    int i = blockIdx.x * blockDim.x + threadIdx.x;
    for (; i < nedges; i += gridDim.x * blockDim.x)
        atomicAdd(&g_deg[ei[nedges + i]], 1);
}

// ---------------------------------------------------------------------------
// K2: exclusive prefix sum over 50000 degrees (single block, 1024 threads)
// ---------------------------------------------------------------------------
__global__ void k_prefix() {
    __shared__ int sums[1024];
    const int CH = (NNODES + 1023) / 1024;   // 49
    int t = threadIdx.x;
    int beg = t * CH, end = min(beg + CH, NNODES);
    int s = 0;
    for (int i = beg; i < end; i++) s += g_deg[i];
    sums[t] = s;
    __syncthreads();
    for (int off = 1; off < 1024; off <<= 1) {
        int add = (t >= off) ? sums[t - off] : 0;
        __syncthreads();
        sums[t] += add;
        __syncthreads();
    }
    int run = sums[t] - s;   // exclusive base
    for (int i = beg; i < end; i++) {
        g_off[i] = run; g_cursor[i] = run;
        run += g_deg[i];
    }
    if (t == 1023) g_off[NNODES] = sums[1023];
}

// ---------------------------------------------------------------------------
// K3: merged GEMM (support = x@W, f32x2 packed, 8 rows/thread) + CSR fill.
// Blocks [0,GEMM_BLKS): GEMM.  Blocks [GEMM_BLKS, ..): bucket fill.
// ---------------------------------------------------------------------------
#define GEMM_BLKS 1250
#define FILL_BLKS 1024

__global__ void k_gemm_fill(const float* __restrict__ x, const float* __restrict__ W,
                            const int* __restrict__ ei, int nedges) {
    if (blockIdx.x >= GEMM_BLKS) {
        // -------- CSR bucket fill --------
        int i = (blockIdx.x - GEMM_BLKS) * blockDim.x + threadIdx.x;
        for (; i < nedges; i += FILL_BLKS * blockDim.x) {
            int src = ei[i];
            int dst = ei[nedges + i];
            int p = atomicAdd(&g_cursor[dst], 1);
            g_adj[p] = src;
        }
        return;
    }
    // -------- GEMM --------
    extern __shared__ float sm[];
    float*      Ws  = sm;                                  // 16384 floats
    float4*     xs4 = (float4*)(sm + DH * DH);             // 256 * 2 float4 (8KB)

    int tid  = threadIdx.x;
    int half = tid >> 7;
    int t    = tid & 127;

    for (int i = tid; i < DH * DH; i += blockDim.x) Ws[i] = W[i];

    for (int row0 = blockIdx.x * 16; row0 < TOTROWS; row0 += GEMM_BLKS * 16) {
        int r0 = row0 + half * 8;
        float v[8];
        #pragma unroll
        for (int rr = 0; rr < 8; rr++)
            v[rr] = x[(size_t)(r0 + rr) * DH + t];
        __syncthreads();                   // prior iter reads done (covers Ws iter 0)
        xs4[(half * DH + t) * 2 + 0] = make_float4(v[0], v[1], v[2], v[3]);
        xs4[(half * DH + t) * 2 + 1] = make_float4(v[4], v[5], v[6], v[7]);
        __syncthreads();

        ull acc[4] = {0ull, 0ull, 0ull, 0ull};
        const ulonglong2* xh = (const ulonglong2*)(xs4 + half * DH * 2);
        #pragma unroll 4
        for (int d = 0; d < DH; d++) {
            float w = Ws[d * DH + t];
            ull ww = pack2(w, w);
            ulonglong2 pA = xh[d * 2 + 0];
            ulonglong2 pB = xh[d * 2 + 1];
            ffma2(acc[0], pA.x, ww);
            ffma2(acc[1], pA.y, ww);
            ffma2(acc[2], pB.x, ww);
            ffma2(acc[3], pB.y, ww);
        }
        #pragma unroll
        for (int q = 0; q < 4; q++) {
            float f0, f1; unpack2(acc[q], f0, f1);
            g_support[(size_t)(r0 + 2 * q)     * DH + t] = f0;
            g_support[(size_t)(r0 + 2 * q + 1) * DH + t] = f1;
        }
    }
}

// ---------------------------------------------------------------------------
// K4: fused gather-aggregate + GELU + MLP + mean-reduce + finalize.
// One warp per node; both batches share the adjacency walk.
// ---------------------------------------------------------------------------
#define FUSED_BLKS 592

__global__ void k_fused(const float* __restrict__ b,
                        const float* __restrict__ W1, const float* __restrict__ b1,
                        const float* __restrict__ W2, const float* __restrict__ b2,
                        const float* __restrict__ W3, const float* __restrict__ b3,
                        float* __restrict__ out) {
    extern __shared__ float sm[];
    float* W1s  = sm;              // 8192  [128][64] row-major
    float* W2t  = W1s + 8192;      // 2048  [32 out][64 in]  (transposed)
    float* W3s  = W2t + 2048;      // 320   [32][10]
    float* bs   = W3s + 320;       // 128
    float* b1s  = bs  + 128;       // 64
    float* b2s  = b1s + 64;        // 32
    float* b3s  = b2s + 32;        // 16
    float* accs = b3s + 16;        // 32
    float* bufs = accs + 32;       // 8 warps * 352 (hh:256, h1:64, h2:32)

    int tid = threadIdx.x;
    for (int i = tid; i < 8192; i += blockDim.x) W1s[i] = W1[i];
    for (int i = tid; i < 2048; i += blockDim.x) {
        int o = i >> 6, in = i & 63;
        W2t[i] = W2[in * 32 + o];
    }
    for (int i = tid; i < 320; i += blockDim.x) W3s[i] = W3[i];
    if (tid < 128) bs[tid]  = b[tid];
    if (tid < 64)  b1s[tid] = b1[tid];
    if (tid < 32)  b2s[tid] = b2[tid];
    if (tid < 16)  b3s[tid] = (tid < 10) ? b3[tid] : 0.f;
    if (tid < 32)  accs[tid] = 0.f;
    __syncthreads();

    int w    = tid >> 5;
    int lane = tid & 31;
    ull*   hhb = (ull*)(bufs + w * 352);   // 128 duplicated pairs
    float* h1b = bufs + w * 352 + 256;     // 64
    float* h2b = h1b + 64;                 // 32

    float4 bb  = ((const float4*)bs)[lane];
    ull    b1p = ((const ull*)b1s)[lane];
    float  b2a = b2s[lane];
    float  b3a = (lane < 10) ? b3s[lane] : 0.f;

    int nwarps = FUSED_BLKS * 8;
    int gw = blockIdx.x * 8 + w;

    float accB0 = 0.f, accB1 = 0.f;

    for (int node = gw; node < NNODES; node += nwarps) {
        int beg = g_off[node];
        int end = g_off[node + 1];

        float4 a0 = make_float4(0.f, 0.f, 0.f, 0.f);
        float4 a1 = make_float4(0.f, 0.f, 0.f, 0.f);
        const float4* sup = (const float4*)g_support;
        #pragma unroll 2
        for (int j = beg; j < end; j++) {
            int src = __ldg(&g_adj[j]);
            float4 v0 = __ldg(sup + (size_t)src * 32 + lane);
            float4 v1 = __ldg(sup + ((size_t)NNODES + src) * 32 + lane);
            a0.x += v0.x; a0.y += v0.y; a0.z += v0.z; a0.w += v0.w;
            a1.x += v1.x; a1.y += v1.y; a1.z += v1.z; a1.w += v1.w;
        }

        #pragma unroll
        for (int bt = 0; bt < 2; bt++) {
            float4 a = (bt == 0) ? a0 : a1;
            // h = gelu(agg + b), stored as duplicated pairs for FFMA2
            float g0 = gelu_exact(a.x + bb.x);
            float g1 = gelu_exact(a.y + bb.y);
            float g2 = gelu_exact(a.z + bb.z);
            float g3 = gelu_exact(a.w + bb.w);
            ulonglong2* hh2 = (ulonglong2*)hhb;
            hh2[2 * lane + 0] = make_ulonglong2(pack2(g0, g0), pack2(g1, g1));
            hh2[2 * lane + 1] = make_ulonglong2(pack2(g2, g2), pack2(g3, g3));
            __syncwarp();

            // layer1: outputs (2*lane, 2*lane+1), packed
            ull s = b1p;
            const ull* w1p = (const ull*)W1s + lane;
            #pragma unroll 8
            for (int j = 0; j < 128; j++)
                ffma2(s, hhb[j], w1p[j * 32]);
            float r0, r1; unpack2(s, r0, r1);
            r0 = fmaxf(r0, 0.f); r1 = fmaxf(r1, 0.f);
            ((ull*)h1b)[lane] = pack2(r0, r1);
            __syncwarp();

            // layer2: output `lane`, packed over input pairs (W2 transposed)
            ull s2 = pack2(b2a, 0.f);
            const ull* h1u = (const ull*)h1b;
            const ull* w2u = (const ull*)(W2t + lane * 64);
            #pragma unroll 8
            for (int j = 0; j < 32; j++)
                ffma2(s2, h1u[j], w2u[j]);
            float e0, e1; unpack2(s2, e0, e1);
            h2b[lane] = fmaxf(e0 + e1, 0.f);
            __syncwarp();

            // layer3: lanes 0..9 each produce one output
            if (lane < 10) {
                float s4 = b3a;
                #pragma unroll
                for (int j = 0; j < 32; j++)
                    s4 = fmaf(h2b[j], W3s[j * 10 + lane], s4);
                if (bt == 0) accB0 += s4; else accB1 += s4;
            }
            __syncwarp();
        }
    }

    // block reduce -> global accumulate -> last block finalizes
    if (lane < 10) {
        atomicAdd(&accs[lane],      accB0);
        atomicAdd(&accs[10 + lane], accB1);
    }
    __syncthreads();
    if (tid < 20) atomicAdd(&g_acc[tid], accs[tid]);
    __threadfence();
    __syncthreads();
    if (tid == 0) {
        unsigned int prev = atomicAdd(&g_done, 1u);
        if (prev == (unsigned int)(gridDim.x - 1)) {
            #pragma unroll
            for (int i = 0; i < 20; i++)
                out[i] = __ldcg(&g_acc[i]) * (1.0f / (float)NNODES);
        }
    }
}

// ---------------------------------------------------------------------------
extern "C" void kernel_launch(void* const* d_in, const int* in_sizes, int n_in,
                              void* d_out, int out_size) {
    const float* x  = (const float*)d_in[0];
    const int*   ei = (const int*)  d_in[1];
    const float* W  = (const float*)d_in[2];
    const float* b  = (const float*)d_in[3];
    const float* W1 = (const float*)d_in[4];
    const float* b1 = (const float*)d_in[5];
    const float* W2 = (const float*)d_in[6];
    const float* b2 = (const float*)d_in[7];
    const float* W3 = (const float*)d_in[8];
    const float* b3 = (const float*)d_in[9];
    float* out = (float*)d_out;

    int nedges = in_sizes[1] / 2;

    const int GEMM_SMEM  = (DH * DH + 256 * 8) * (int)sizeof(float);   // 73728
    const int FUSED_SMEM = (8192 + 2048 + 320 + 128 + 64 + 32 + 16 + 32 + 8 * 352)
                           * (int)sizeof(float);                        // 54592

    cudaFuncSetAttribute(k_gemm_fill, cudaFuncAttributeMaxDynamicSharedMemorySize, GEMM_SMEM);
    cudaFuncSetAttribute(k_fused,     cudaFuncAttributeMaxDynamicSharedMemorySize, FUSED_SMEM);

    k_zero  <<<98, 512>>>();
    k_hist  <<<1024, 256>>>(ei, nedges);
    k_prefix<<<1, 1024>>>();
    k_gemm_fill<<<GEMM_BLKS + FILL_BLKS, 256, GEMM_SMEM>>>(x, W, ei, nedges);
    k_fused <<<FUSED_BLKS, 256, FUSED_SMEM>>>(b, W1, b1, W2, b2, W3, b3, out);
}

// round 4
// speedup vs baseline: 1.4827x; 1.4827x over previous
#include <cuda_runtime.h>
#include <math.h>

#define NNODES  50000
#define DH      128
#define TOTROWS (2 * NNODES)
#define MAXE    800000

typedef unsigned long long ull;

// ---- device scratch ----
__device__ float g_support[(size_t)TOTROWS * DH];
__device__ int   g_deg[NNODES];
__device__ int   g_off[NNODES + 1];
__device__ int   g_cursor[NNODES];
__device__ int   g_adj[MAXE];
__device__ float g_acc[32];
__device__ unsigned int g_done;

// ---- packed fp32x2 helpers ----
__device__ __forceinline__ ull pack2(float a, float b) {
    ull r; asm("mov.b64 %0, {%1, %2};" : "=l"(r) : "f"(a), "f"(b)); return r;
}
__device__ __forceinline__ void unpack2(ull v, float& a, float& b) {
    asm("mov.b64 {%0, %1}, %2;" : "=f"(a), "=f"(b) : "l"(v));
}
__device__ __forceinline__ void ffma2(ull& d, ull a, ull b) {
    asm("fma.rn.f32x2 %0, %1, %2, %0;" : "+l"(d) : "l"(a), "l"(b));
}
__device__ __forceinline__ float gelu_exact(float v) {
    return 0.5f * v * (1.0f + erff(v * 0.70710678118654752f));
}

// ---------------------------------------------------------------------------
// K0: zero histogram + accumulators
// ---------------------------------------------------------------------------
__global__ void k_zero() {
    int i = blockIdx.x * blockDim.x + threadIdx.x;
    for (; i < NNODES; i += gridDim.x * blockDim.x) g_deg[i] = 0;
    if (blockIdx.x == 0 && threadIdx.x < 32) g_acc[threadIdx.x] = 0.f;
    if (blockIdx.x == 0 && threadIdx.x == 0) g_done = 0u;
}

// ---------------------------------------------------------------------------
// K1: histogram of dst
// ---------------------------------------------------------------------------
__global__ void k_hist(const int* __restrict__ ei, int nedges) {
    int i = blockIdx.x * blockDim.x + threadIdx.x;
    for (; i < nedges; i += gridDim.x * blockDim.x)
        atomicAdd(&g_deg[ei[nedges + i]], 1);
}

// ---------------------------------------------------------------------------
// K2: exclusive prefix over degrees (1 block, 1024 threads)
// ---------------------------------------------------------------------------
__global__ void k_prefix() {
    __shared__ int sums[1024];
    const int CH = (NNODES + 1023) / 1024;
    int t = threadIdx.x;
    int beg = t * CH, end = min(beg + CH, NNODES);
    int s = 0;
    for (int i = beg; i < end; i++) s += g_deg[i];
    sums[t] = s;
    __syncthreads();
    for (int off = 1; off < 1024; off <<= 1) {
        int add = (t >= off) ? sums[t - off] : 0;
        __syncthreads();
        sums[t] += add;
        __syncthreads();
    }
    int run = sums[t] - s;
    for (int i = beg; i < end; i++) {
        g_off[i] = run; g_cursor[i] = run;
        run += g_deg[i];
    }
    if (t == 1023) g_off[NNODES] = sums[1023];
}

// ---------------------------------------------------------------------------
// K3: CSR bucket fill
// ---------------------------------------------------------------------------
__global__ void k_fill(const int* __restrict__ ei, int nedges) {
    int i = blockIdx.x * blockDim.x + threadIdx.x;
    for (; i < nedges; i += gridDim.x * blockDim.x) {
        int src = ei[i];
        int dst = ei[nedges + i];
        int p = atomicAdd(&g_cursor[dst], 1);
        g_adj[p] = src;
    }
}

// ---------------------------------------------------------------------------
// K4: GEMM support = x @ W.  Block tile 64 rows x 128 cols.
// Thread = 8 rows (4 f32x2 pairs) x 4 cols = 16 packed accumulators.
// Warp ty = row-group (rows ty*8..+7); lane spans cols (4*lane..+3).
// Per d: 1 LDS.128 (W row) + 4 LDS.64 broadcast (x pairs) -> 16 FFMA2.
// ---------------------------------------------------------------------------
#define XS_STRIDE 66   // floats per d-row in xsT (pad: 2-way conflict only)

__global__ void __launch_bounds__(256, 2)
k_gemm(const float* __restrict__ x, const float* __restrict__ W) {
    extern __shared__ float sm[];
    float* Ws  = sm;                 // 128*128 = 16384 floats (64KB)
    float* xsT = sm + DH * DH;       // 128 * 66 floats (~33.8KB)

    int tid  = threadIdx.x;
    int ty   = tid >> 5;             // warp / row-group (0..7)
    int lane = tid & 31;             // col-group (cols 4*lane..4*lane+3)

    // stage W (row-major, coalesced float4)
    for (int i = tid; i < DH * DH / 4; i += 256)
        ((float4*)Ws)[i] = ((const float4*)W)[i];

    int row0 = blockIdx.x * 64;

    // stage x tile transposed: xsT[d][r] = x[row0+r][d]
    {
        int d  = tid & 127;
        int rh = tid >> 7;           // 0 or 1
        #pragma unroll 8
        for (int rr = 0; rr < 32; rr++) {
            int r = rr * 2 + rh;
            int row = row0 + r;
            float v = (row < TOTROWS) ? x[(size_t)row * DH + d] : 0.f;
            xsT[d * XS_STRIDE + r] = v;
        }
    }
    __syncthreads();

    ull acc[4][4];
    #pragma unroll
    for (int rp = 0; rp < 4; rp++)
        #pragma unroll
        for (int c = 0; c < 4; c++) acc[rp][c] = 0ull;

    const ull* xrow = (const ull*)(xsT + ty * 8);  // pairs at d*33 + rp (in ull units)
    #pragma unroll 4
    for (int d = 0; d < DH; d++) {
        float4 w4 = *(const float4*)(Ws + d * DH + 4 * lane);
        ull ww0 = pack2(w4.x, w4.x);
        ull ww1 = pack2(w4.y, w4.y);
        ull ww2 = pack2(w4.z, w4.z);
        ull ww3 = pack2(w4.w, w4.w);
        const ull* xp = (const ull*)(xsT + d * XS_STRIDE + ty * 8);
        ull x0 = xp[0], x1 = xp[1], x2 = xp[2], x3 = xp[3];
        ffma2(acc[0][0], x0, ww0); ffma2(acc[0][1], x0, ww1);
        ffma2(acc[0][2], x0, ww2); ffma2(acc[0][3], x0, ww3);
        ffma2(acc[1][0], x1, ww0); ffma2(acc[1][1], x1, ww1);
        ffma2(acc[1][2], x1, ww2); ffma2(acc[1][3], x1, ww3);
        ffma2(acc[2][0], x2, ww0); ffma2(acc[2][1], x2, ww1);
        ffma2(acc[2][2], x2, ww2); ffma2(acc[2][3], x2, ww3);
        ffma2(acc[3][0], x3, ww0); ffma2(acc[3][1], x3, ww1);
        ffma2(acc[3][2], x3, ww2); ffma2(acc[3][3], x3, ww3);
    }
    (void)xrow;

    // epilogue: rows row0 + ty*8 + 2rp (+1), cols 4*lane..+3
    #pragma unroll
    for (int rp = 0; rp < 4; rp++) {
        float lo0, hi0, lo1, hi1, lo2, hi2, lo3, hi3;
        unpack2(acc[rp][0], lo0, hi0);
        unpack2(acc[rp][1], lo1, hi1);
        unpack2(acc[rp][2], lo2, hi2);
        unpack2(acc[rp][3], lo3, hi3);
        int r = row0 + ty * 8 + 2 * rp;
        if (r < TOTROWS)
            *(float4*)(g_support + (size_t)r * DH + 4 * lane) = make_float4(lo0, lo1, lo2, lo3);
        if (r + 1 < TOTROWS)
            *(float4*)(g_support + (size_t)(r + 1) * DH + 4 * lane) = make_float4(hi0, hi1, hi2, hi3);
    }
}

// ---------------------------------------------------------------------------
// K5: fused CSR gather + GELU + MLP + mean reduce + finalize.
// One warp per node (both batches). Plain fp32, 4 blocks/SM pinned.
// ---------------------------------------------------------------------------
#define FUSED_BLKS 592

__global__ void __launch_bounds__(256, 4)
k_fused(const float* __restrict__ b,
        const float* __restrict__ W1, const float* __restrict__ b1,
        const float* __restrict__ W2, const float* __restrict__ b2,
        const float* __restrict__ W3, const float* __restrict__ b3,
        float* __restrict__ out) {
    extern __shared__ float sm[];
    float* W1s  = sm;             // 8192
    float* W2s  = W1s + 8192;     // 2048
    float* W3s  = W2s + 2048;     // 320
    float* bs   = W3s + 320;      // 128
    float* b1s  = bs  + 128;      // 64
    float* b2s  = b1s + 64;       // 32
    float* b3s  = b2s + 32;       // 16
    float* accs = b3s + 16;       // 32
    float* bufs = accs + 32;      // 8 warps * 224

    int tid = threadIdx.x;
    for (int i = tid; i < 8192; i += 256) W1s[i] = W1[i];
    for (int i = tid; i < 2048; i += 256) W2s[i] = W2[i];
    for (int i = tid; i < 320;  i += 256) W3s[i] = W3[i];
    if (tid < 128) bs[tid]  = b[tid];
    if (tid < 64)  b1s[tid] = b1[tid];
    if (tid < 32)  b2s[tid] = b2[tid];
    if (tid < 16)  b3s[tid] = (tid < 10) ? b3[tid] : 0.f;
    if (tid < 32)  accs[tid] = 0.f;
    __syncthreads();

    int w    = tid >> 5;
    int lane = tid & 31;
    float* hb  = bufs + w * 224;
    float* h1b = hb + 128;
    float* h2b = h1b + 64;

    float4 bb  = ((const float4*)bs)[lane];
    float2 b1v = ((const float2*)b1s)[lane];
    float  b2a = b2s[lane];
    float  b3a = (lane < 10) ? b3s[lane] : 0.f;

    const int nwarps = FUSED_BLKS * 8;
    int gw = blockIdx.x * 8 + w;

    float accB0 = 0.f, accB1 = 0.f;

    for (int node = gw; node < NNODES; node += nwarps) {
        int beg = g_off[node];
        int end = g_off[node + 1];

        float4 a0 = make_float4(0.f, 0.f, 0.f, 0.f);
        float4 a1 = make_float4(0.f, 0.f, 0.f, 0.f);
        const float4* sup = (const float4*)g_support;
        #pragma unroll 2
        for (int j = beg; j < end; j++) {
            int src = __ldg(&g_adj[j]);
            float4 v0 = __ldg(sup + (size_t)src * 32 + lane);
            float4 v1 = __ldg(sup + ((size_t)NNODES + src) * 32 + lane);
            a0.x += v0.x; a0.y += v0.y; a0.z += v0.z; a0.w += v0.w;
            a1.x += v1.x; a1.y += v1.y; a1.z += v1.z; a1.w += v1.w;
        }

        #pragma unroll
        for (int bt = 0; bt < 2; bt++) {
            float4 a = (bt == 0) ? a0 : a1;
            a.x = gelu_exact(a.x + bb.x);
            a.y = gelu_exact(a.y + bb.y);
            a.z = gelu_exact(a.z + bb.z);
            a.w = gelu_exact(a.w + bb.w);
            ((float4*)hb)[lane] = a;
            __syncwarp();

            // layer1: outputs (2*lane, 2*lane+1)
            float2 s = b1v;
            const float4* hb4 = (const float4*)hb;
            const float2* w1p = (const float2*)W1s + lane;
            #pragma unroll 8
            for (int j4 = 0; j4 < 32; j4++) {
                float4 h4 = hb4[j4];
                float2 q0 = w1p[(j4 * 4 + 0) * 32];
                float2 q1 = w1p[(j4 * 4 + 1) * 32];
                float2 q2 = w1p[(j4 * 4 + 2) * 32];
                float2 q3 = w1p[(j4 * 4 + 3) * 32];
                s.x = fmaf(h4.x, q0.x, s.x); s.y = fmaf(h4.x, q0.y, s.y);
                s.x = fmaf(h4.y, q1.x, s.x); s.y = fmaf(h4.y, q1.y, s.y);
                s.x = fmaf(h4.z, q2.x, s.x); s.y = fmaf(h4.z, q2.y, s.y);
                s.x = fmaf(h4.w, q3.x, s.x); s.y = fmaf(h4.w, q3.y, s.y);
            }
            s.x = fmaxf(s.x, 0.f);
            s.y = fmaxf(s.y, 0.f);
            ((float2*)h1b)[lane] = s;
            __syncwarp();

            // layer2: output `lane`
            float s3 = b2a;
            const float4* h1b4 = (const float4*)h1b;
            #pragma unroll 4
            for (int j4 = 0; j4 < 16; j4++) {
                float4 h4 = h1b4[j4];
                s3 = fmaf(h4.x, W2s[(j4 * 4 + 0) * 32 + lane], s3);
                s3 = fmaf(h4.y, W2s[(j4 * 4 + 1) * 32 + lane], s3);
                s3 = fmaf(h4.z, W2s[(j4 * 4 + 2) * 32 + lane], s3);
                s3 = fmaf(h4.w, W2s[(j4 * 4 + 3) * 32 + lane], s3);
            }
            h2b[lane] = fmaxf(s3, 0.f);
            __syncwarp();

            // layer3: lanes 0..9
            if (lane < 10) {
                float s4 = b3a;
                #pragma unroll
                for (int j = 0; j < 32; j++)
                    s4 = fmaf(h2b[j], W3s[j * 10 + lane], s4);
                if (bt == 0) accB0 += s4; else accB1 += s4;
            }
            __syncwarp();
        }
    }

    if (lane < 10) {
        atomicAdd(&accs[lane],      accB0);
        atomicAdd(&accs[10 + lane], accB1);
    }
    __syncthreads();
    if (tid < 20) atomicAdd(&g_acc[tid], accs[tid]);
    __threadfence();
    __syncthreads();
    if (tid == 0) {
        unsigned int prev = atomicAdd(&g_done, 1u);
        if (prev == (unsigned int)(gridDim.x - 1)) {
            #pragma unroll
            for (int i = 0; i < 20; i++)
                out[i] = __ldcg(&g_acc[i]) * (1.0f / (float)NNODES);
        }
    }
}

// ---------------------------------------------------------------------------
extern "C" void kernel_launch(void* const* d_in, const int* in_sizes, int n_in,
                              void* d_out, int out_size) {
    const float* x  = (const float*)d_in[0];
    const int*   ei = (const int*)  d_in[1];
    const float* W  = (const float*)d_in[2];
    const float* b  = (const float*)d_in[3];
    const float* W1 = (const float*)d_in[4];
    const float* b1 = (const float*)d_in[5];
    const float* W2 = (const float*)d_in[6];
    const float* b2 = (const float*)d_in[7];
    const float* W3 = (const float*)d_in[8];
    const float* b3 = (const float*)d_in[9];
    float* out = (float*)d_out;

    int nedges = in_sizes[1] / 2;

    const int GEMM_SMEM  = (DH * DH + DH * XS_STRIDE) * (int)sizeof(float);  // 99328
    const int FUSED_SMEM = (8192 + 2048 + 320 + 128 + 64 + 32 + 16 + 32 + 8 * 224)
                           * (int)sizeof(float);                              // 50496

    cudaFuncSetAttribute(k_gemm,  cudaFuncAttributeMaxDynamicSharedMemorySize, GEMM_SMEM);
    cudaFuncSetAttribute(k_fused, cudaFuncAttributeMaxDynamicSharedMemorySize, FUSED_SMEM);

    k_zero  <<<98, 512>>>();
    k_hist  <<<1024, 256>>>(ei, nedges);
    k_prefix<<<1, 1024>>>();
    k_fill  <<<1024, 256>>>(ei, nedges);
    k_gemm  <<<(TOTROWS + 63) / 64, 256, GEMM_SMEM>>>(x, W);
    k_fused <<<FUSED_BLKS, 256, FUSED_SMEM>>>(b, W1, b1, W2, b2, W3, b3, out);
}

// round 6
// speedup vs baseline: 1.6544x; 1.1158x over previous
#include <cuda_runtime.h>
#include <cuda_bf16.h>
#include <math.h>

#define NNODES  50000
#define DH      128
#define TOTROWS (2 * NNODES)
#define MAXE    800000

typedef unsigned long long ull;
typedef unsigned int u32;

// ---- device scratch ----
__device__ u32   g_support[(size_t)TOTROWS * DH / 2];   // bf16x2 pairs
__device__ int   g_deg[NNODES];
__device__ int   g_off[NNODES + 1];
__device__ int   g_cursor[NNODES];
__device__ int   g_adj[MAXE];
__device__ float g_acc[32];
__device__ unsigned int g_done;

// ---- packed fp32x2 helpers ----
__device__ __forceinline__ ull pack2(float a, float b) {
    ull r; asm("mov.b64 %0, {%1, %2};" : "=l"(r) : "f"(a), "f"(b)); return r;
}
__device__ __forceinline__ void unpack2(ull v, float& a, float& b) {
    asm("mov.b64 {%0, %1}, %2;" : "=f"(a), "=f"(b) : "l"(v));
}
__device__ __forceinline__ void ffma2(ull& d, ull a, ull b) {
    asm("fma.rn.f32x2 %0, %1, %2, %0;" : "+l"(d) : "l"(a), "l"(b));
}
// pack two fp32 -> bf16x2 (lo in low half, hi in high half)
__device__ __forceinline__ u32 pack_bf16(float lo, float hi) {
    u32 r; asm("cvt.rn.bf16x2.f32 %0, %1, %2;" : "=r"(r) : "f"(hi), "f"(lo)); return r;
}
// bf16x2 decode: low half, high half as fp32 (bf16 == fp32 top 16 bits)
__device__ __forceinline__ float bf_lo(u32 v) { return __uint_as_float(v << 16); }
__device__ __forceinline__ float bf_hi(u32 v) { return __uint_as_float(v & 0xffff0000u); }

__device__ __forceinline__ float gelu_exact(float v) {
    return 0.5f * v * (1.0f + erff(v * 0.70710678118654752f));
}

// ---------------------------------------------------------------------------
// K0: zero histogram + accumulators
// ---------------------------------------------------------------------------
__global__ void k_zero() {
    int i = blockIdx.x * blockDim.x + threadIdx.x;
    for (; i < NNODES; i += gridDim.x * blockDim.x) g_deg[i] = 0;
    if (blockIdx.x == 0 && threadIdx.x < 32) g_acc[threadIdx.x] = 0.f;
    if (blockIdx.x == 0 && threadIdx.x == 0) g_done = 0u;
}

// ---------------------------------------------------------------------------
// K1: histogram of dst
// ---------------------------------------------------------------------------
__global__ void k_hist(const int* __restrict__ ei, int nedges) {
    int i = blockIdx.x * blockDim.x + threadIdx.x;
    for (; i < nedges; i += gridDim.x * blockDim.x)
        atomicAdd(&g_deg[ei[nedges + i]], 1);
}

// ---------------------------------------------------------------------------
// K2: exclusive prefix over degrees (1 block, 1024 threads)
// ---------------------------------------------------------------------------
__global__ void k_prefix() {
    __shared__ int sums[1024];
    const int CH = (NNODES + 1023) / 1024;
    int t = threadIdx.x;
    int beg = t * CH, end = min(beg + CH, NNODES);
    int s = 0;
    for (int i = beg; i < end; i++) s += g_deg[i];
    sums[t] = s;
    __syncthreads();
    for (int off = 1; off < 1024; off <<= 1) {
        int add = (t >= off) ? sums[t - off] : 0;
        __syncthreads();
        sums[t] += add;
        __syncthreads();
    }
    int run = sums[t] - s;
    for (int i = beg; i < end; i++) {
        g_off[i] = run; g_cursor[i] = run;
        run += g_deg[i];
    }
    if (t == 1023) g_off[NNODES] = sums[1023];
}

// ---------------------------------------------------------------------------
// K3: CSR bucket fill
// ---------------------------------------------------------------------------
__global__ void k_fill(const int* __restrict__ ei, int nedges) {
    int i = blockIdx.x * blockDim.x + threadIdx.x;
    for (; i < nedges; i += gridDim.x * blockDim.x) {
        int src = ei[i];
        int dst = ei[nedges + i];
        int p = atomicAdd(&g_cursor[dst], 1);
        g_adj[p] = src;
    }
}

// ---------------------------------------------------------------------------
// K4: GEMM support = x @ W (fp32 accum, bf16 output).
// Block tile 64 rows x 128 cols; thread = 8 rows (4 f32x2 pairs) x 4 cols.
// ---------------------------------------------------------------------------
#define XS_STRIDE 66

__global__ void __launch_bounds__(256, 2)
k_gemm(const float* __restrict__ x, const float* __restrict__ W) {
    extern __shared__ float sm[];
    float* Ws  = sm;                 // 16384 floats
    float* xsT = sm + DH * DH;       // 128 * 66 floats

    int tid  = threadIdx.x;
    int ty   = tid >> 5;
    int lane = tid & 31;

    for (int i = tid; i < DH * DH / 4; i += 256)
        ((float4*)Ws)[i] = ((const float4*)W)[i];

    int row0 = blockIdx.x * 64;

    {
        int d  = tid & 127;
        int rh = tid >> 7;
        #pragma unroll 8
        for (int rr = 0; rr < 32; rr++) {
            int r = rr * 2 + rh;
            int row = row0 + r;
            float v = (row < TOTROWS) ? x[(size_t)row * DH + d] : 0.f;
            xsT[d * XS_STRIDE + r] = v;
        }
    }
    __syncthreads();

    ull acc[4][4];
    #pragma unroll
    for (int rp = 0; rp < 4; rp++)
        #pragma unroll
        for (int c = 0; c < 4; c++) acc[rp][c] = 0ull;

    #pragma unroll 4
    for (int d = 0; d < DH; d++) {
        float4 w4 = *(const float4*)(Ws + d * DH + 4 * lane);
        ull ww0 = pack2(w4.x, w4.x);
        ull ww1 = pack2(w4.y, w4.y);
        ull ww2 = pack2(w4.z, w4.z);
        ull ww3 = pack2(w4.w, w4.w);
        const ull* xp = (const ull*)(xsT + d * XS_STRIDE + ty * 8);
        ull x0 = xp[0], x1 = xp[1], x2 = xp[2], x3 = xp[3];
        ffma2(acc[0][0], x0, ww0); ffma2(acc[0][1], x0, ww1);
        ffma2(acc[0][2], x0, ww2); ffma2(acc[0][3], x0, ww3);
        ffma2(acc[1][0], x1, ww0); ffma2(acc[1][1], x1, ww1);
        ffma2(acc[1][2], x1, ww2); ffma2(acc[1][3], x1, ww3);
        ffma2(acc[2][0], x2, ww0); ffma2(acc[2][1], x2, ww1);
        ffma2(acc[2][2], x2, ww2); ffma2(acc[2][3], x2, ww3);
        ffma2(acc[3][0], x3, ww0); ffma2(acc[3][1], x3, ww1);
        ffma2(acc[3][2], x3, ww2); ffma2(acc[3][3], x3, ww3);
    }

    // epilogue: convert to bf16, 4 cols per row -> uint2 store (8B)
    #pragma unroll
    for (int rp = 0; rp < 4; rp++) {
        float lo0, hi0, lo1, hi1, lo2, hi2, lo3, hi3;
        unpack2(acc[rp][0], lo0, hi0);
        unpack2(acc[rp][1], lo1, hi1);
        unpack2(acc[rp][2], lo2, hi2);
        unpack2(acc[rp][3], lo3, hi3);
        int r = row0 + ty * 8 + 2 * rp;
        if (r < TOTROWS) {
            uint2 v = make_uint2(pack_bf16(lo0, lo1), pack_bf16(lo2, lo3));
            *(uint2*)(g_support + (size_t)r * 64 + 2 * lane) = v;
        }
        if (r + 1 < TOTROWS) {
            uint2 v = make_uint2(pack_bf16(hi0, hi1), pack_bf16(hi2, hi3));
            *(uint2*)(g_support + (size_t)(r + 1) * 64 + 2 * lane) = v;
        }
    }
}

// ---------------------------------------------------------------------------
// K5: fused CSR gather (bf16 support) + GELU + MLP + mean reduce + finalize.
// One warp per node (both batches); fp32 math; 4 blocks/SM pinned.
// ---------------------------------------------------------------------------
#define FUSED_BLKS 592

__global__ void __launch_bounds__(256, 4)
k_fused(const float* __restrict__ b,
        const float* __restrict__ W1, const float* __restrict__ b1,
        const float* __restrict__ W2, const float* __restrict__ b2,
        const float* __restrict__ W3, const float* __restrict__ b3,
        float* __restrict__ out) {
    extern __shared__ float sm[];
    float* W1s  = sm;             // 8192
    float* W2s  = W1s + 8192;     // 2048
    float* W3s  = W2s + 2048;     // 320
    float* bs   = W3s + 320;      // 128
    float* b1s  = bs  + 128;      // 64
    float* b2s  = b1s + 64;       // 32
    float* b3s  = b2s + 32;       // 16
    float* accs = b3s + 16;       // 32
    float* bufs = accs + 32;      // 8 warps * 224

    int tid = threadIdx.x;
    for (int i = tid; i < 8192; i += 256) W1s[i] = W1[i];
    for (int i = tid; i < 2048; i += 256) W2s[i] = W2[i];
    for (int i = tid; i < 320;  i += 256) W3s[i] = W3[i];
    if (tid < 128) bs[tid]  = b[tid];
    if (tid < 64)  b1s[tid] = b1[tid];
    if (tid < 32)  b2s[tid] = b2[tid];
    if (tid < 16)  b3s[tid] = (tid < 10) ? b3[tid] : 0.f;
    if (tid < 32)  accs[tid] = 0.f;
    __syncthreads();

    int w    = tid >> 5;
    int lane = tid & 31;
    float* hb  = bufs + w * 224;
    float* h1b = hb + 128;
    float* h2b = h1b + 64;

    float4 bb  = ((const float4*)bs)[lane];
    float2 b1v = ((const float2*)b1s)[lane];
    float  b2a = b2s[lane];
    float  b3a = (lane < 10) ? b3s[lane] : 0.f;

    const int nwarps = FUSED_BLKS * 8;
    int gw = blockIdx.x * 8 + w;

    float accB0 = 0.f, accB1 = 0.f;

    for (int node = gw; node < NNODES; node += nwarps) {
        int beg = g_off[node];
        int end = g_off[node + 1];

        float4 a0 = make_float4(0.f, 0.f, 0.f, 0.f);
        float4 a1 = make_float4(0.f, 0.f, 0.f, 0.f);
        const uint2* sup = (const uint2*)g_support;   // 32 uint2 per row
        #pragma unroll 2
        for (int j = beg; j < end; j++) {
            int src = __ldg(&g_adj[j]);
            uint2 u0 = __ldg(sup + (size_t)src * 32 + lane);
            uint2 u1 = __ldg(sup + ((size_t)NNODES + src) * 32 + lane);
            a0.x += bf_lo(u0.x); a0.y += bf_hi(u0.x);
            a0.z += bf_lo(u0.y); a0.w += bf_hi(u0.y);
            a1.x += bf_lo(u1.x); a1.y += bf_hi(u1.x);
            a1.z += bf_lo(u1.y); a1.w += bf_hi(u1.y);
        }

        #pragma unroll
        for (int bt = 0; bt < 2; bt++) {
            float4 a = (bt == 0) ? a0 : a1;
            a.x = gelu_exact(a.x + bb.x);
            a.y = gelu_exact(a.y + bb.y);
            a.z = gelu_exact(a.z + bb.z);
            a.w = gelu_exact(a.w + bb.w);
            ((float4*)hb)[lane] = a;
            __syncwarp();

            // layer1: outputs (2*lane, 2*lane+1)
            float2 s = b1v;
            const float4* hb4 = (const float4*)hb;
            const float2* w1p = (const float2*)W1s + lane;
            #pragma unroll 8
            for (int j4 = 0; j4 < 32; j4++) {
                float4 h4 = hb4[j4];
                float2 q0 = w1p[(j4 * 4 + 0) * 32];
                float2 q1 = w1p[(j4 * 4 + 1) * 32];
                float2 q2 = w1p[(j4 * 4 + 2) * 32];
                float2 q3 = w1p[(j4 * 4 + 3) * 32];
                s.x = fmaf(h4.x, q0.x, s.x); s.y = fmaf(h4.x, q0.y, s.y);
                s.x = fmaf(h4.y, q1.x, s.x); s.y = fmaf(h4.y, q1.y, s.y);
                s.x = fmaf(h4.z, q2.x, s.x); s.y = fmaf(h4.z, q2.y, s.y);
                s.x = fmaf(h4.w, q3.x, s.x); s.y = fmaf(h4.w, q3.y, s.y);
            }
            s.x = fmaxf(s.x, 0.f);
            s.y = fmaxf(s.y, 0.f);
            ((float2*)h1b)[lane] = s;
            __syncwarp();

            // layer2: output `lane`
            float s3 = b2a;
            const float4* h1b4 = (const float4*)h1b;
            #pragma unroll 4
            for (int j4 = 0; j4 < 16; j4++) {
                float4 h4 = h1b4[j4];
                s3 = fmaf(h4.x, W2s[(j4 * 4 + 0) * 32 + lane], s3);
                s3 = fmaf(h4.y, W2s[(j4 * 4 + 1) * 32 + lane], s3);
                s3 = fmaf(h4.z, W2s[(j4 * 4 + 2) * 32 + lane], s3);
                s3 = fmaf(h4.w, W2s[(j4 * 4 + 3) * 32 + lane], s3);
            }
            h2b[lane] = fmaxf(s3, 0.f);
            __syncwarp();

            // layer3: lanes 0..9
            if (lane < 10) {
                float s4 = b3a;
                #pragma unroll
                for (int j = 0; j < 32; j++)
                    s4 = fmaf(h2b[j], W3s[j * 10 + lane], s4);
                if (bt == 0) accB0 += s4; else accB1 += s4;
            }
            __syncwarp();
        }
    }

    if (lane < 10) {
        atomicAdd(&accs[lane],      accB0);
        atomicAdd(&accs[10 + lane], accB1);
    }
    __syncthreads();
    if (tid < 20) atomicAdd(&g_acc[tid], accs[tid]);
    __threadfence();
    __syncthreads();
    if (tid == 0) {
        unsigned int prev = atomicAdd(&g_done, 1u);
        if (prev == (unsigned int)(gridDim.x - 1)) {
            #pragma unroll
            for (int i = 0; i < 20; i++)
                out[i] = __ldcg(&g_acc[i]) * (1.0f / (float)NNODES);
        }
    }
}

// ---------------------------------------------------------------------------
extern "C" void kernel_launch(void* const* d_in, const int* in_sizes, int n_in,
                              void* d_out, int out_size) {
    const float* x  = (const float*)d_in[0];
    const int*   ei = (const int*)  d_in[1];
    const float* W  = (const float*)d_in[2];
    const float* b  = (const float*)d_in[3];
    const float* W1 = (const float*)d_in[4];
    const float* b1 = (const float*)d_in[5];
    const float* W2 = (const float*)d_in[6];
    const float* b2 = (const float*)d_in[7];
    const float* W3 = (const float*)d_in[8];
    const float* b3 = (const float*)d_in[9];
    float* out = (float*)d_out;

    int nedges = in_sizes[1] / 2;

    const int GEMM_SMEM  = (DH * DH + DH * XS_STRIDE) * (int)sizeof(float);  // 99328
    const int FUSED_SMEM = (8192 + 2048 + 320 + 128 + 64 + 32 + 16 + 32 + 8 * 224)
                           * (int)sizeof(float);                              // 50496

    cudaFuncSetAttribute(k_gemm,  cudaFuncAttributeMaxDynamicSharedMemorySize, GEMM_SMEM);
    cudaFuncSetAttribute(k_fused, cudaFuncAttributeMaxDynamicSharedMemorySize, FUSED_SMEM);

    k_zero  <<<98, 512>>>();
    k_hist  <<<1024, 256>>>(ei, nedges);
    k_prefix<<<1, 1024>>>();
    k_fill  <<<1024, 256>>>(ei, nedges);
    k_gemm  <<<(TOTROWS + 63) / 64, 256, GEMM_SMEM>>>(x, W);
    k_fused <<<FUSED_BLKS, 256, FUSED_SMEM>>>(b, W1, b1, W2, b2, W3, b3, out);
}

// round 8
// speedup vs baseline: 2.0349x; 1.2300x over previous
#include <cuda_runtime.h>
#include <cuda_bf16.h>
#include <math.h>

#define NNODES  50000
#define DH      128
#define TOTROWS (2 * NNODES)
#define MAXE    800000
#define HROWS   100096          // TOTROWS padded to multiple of 128

typedef unsigned long long ull;
typedef unsigned int u32;

// ---- device scratch ----
__device__ u32   g_support[(size_t)TOTROWS * DH / 2];   // bf16x2
__device__ u32   g_h[(size_t)HROWS * 64];               // bf16x2, gelu output
__device__ int   g_deg[NNODES];
__device__ int   g_off[NNODES + 1];
__device__ int   g_cursor[NNODES];
__device__ int   g_adj[MAXE];
__device__ float g_acc2[64];                            // sum of h2 per batch (2x32)
__device__ unsigned int g_done;

// ---- packed helpers ----
__device__ __forceinline__ ull pack2(float a, float b) {
    ull r; asm("mov.b64 %0, {%1, %2};" : "=l"(r) : "f"(a), "f"(b)); return r;
}
__device__ __forceinline__ void unpack2(ull v, float& a, float& b) {
    asm("mov.b64 {%0, %1}, %2;" : "=f"(a), "=f"(b) : "l"(v));
}
__device__ __forceinline__ void ffma2(ull& d, ull a, ull b) {
    asm("fma.rn.f32x2 %0, %1, %2, %0;" : "+l"(d) : "l"(a), "l"(b));
}
__device__ __forceinline__ u32 pack_bf16(float lo, float hi) {
    u32 r; asm("cvt.rn.bf16x2.f32 %0, %1, %2;" : "=r"(r) : "f"(hi), "f"(lo)); return r;
}
__device__ __forceinline__ float bf_lo(u32 v) { return __uint_as_float(v << 16); }
__device__ __forceinline__ float bf_hi(u32 v) { return __uint_as_float(v & 0xffff0000u); }

__device__ __forceinline__ float gelu_exact(float v) {
    return 0.5f * v * (1.0f + erff(v * 0.70710678118654752f));
}

// ---------------------------------------------------------------------------
// K0: zero histogram + accumulators
// ---------------------------------------------------------------------------
__global__ void k_zero() {
    int i = blockIdx.x * blockDim.x + threadIdx.x;
    for (; i < NNODES; i += gridDim.x * blockDim.x) g_deg[i] = 0;
    if (blockIdx.x == 0 && threadIdx.x < 64) g_acc2[threadIdx.x] = 0.f;
    if (blockIdx.x == 0 && threadIdx.x == 0) g_done = 0u;
}

// ---------------------------------------------------------------------------
// K1: histogram of dst
// ---------------------------------------------------------------------------
__global__ void k_hist(const int* __restrict__ ei, int nedges) {
    int i = blockIdx.x * blockDim.x + threadIdx.x;
    for (; i < nedges; i += gridDim.x * blockDim.x)
        atomicAdd(&g_deg[ei[nedges + i]], 1);
}

// ---------------------------------------------------------------------------
// K2: exclusive prefix over degrees
// ---------------------------------------------------------------------------
__global__ void k_prefix() {
    __shared__ int sums[1024];
    const int CH = (NNODES + 1023) / 1024;
    int t = threadIdx.x;
    int beg = t * CH, end = min(beg + CH, NNODES);
    int s = 0;
    for (int i = beg; i < end; i++) s += g_deg[i];
    sums[t] = s;
    __syncthreads();
    for (int off = 1; off < 1024; off <<= 1) {
        int add = (t >= off) ? sums[t - off] : 0;
        __syncthreads();
        sums[t] += add;
        __syncthreads();
    }
    int run = sums[t] - s;
    for (int i = beg; i < end; i++) {
        g_off[i] = run; g_cursor[i] = run;
        run += g_deg[i];
    }
    if (t == 1023) g_off[NNODES] = sums[1023];
}

// ---------------------------------------------------------------------------
// K3: CSR bucket fill
// ---------------------------------------------------------------------------
__global__ void k_fill(const int* __restrict__ ei, int nedges) {
    int i = blockIdx.x * blockDim.x + threadIdx.x;
    for (; i < nedges; i += gridDim.x * blockDim.x) {
        int src = ei[i];
        int dst = ei[nedges + i];
        int p = atomicAdd(&g_cursor[dst], 1);
        g_adj[p] = src;
    }
}

// ---------------------------------------------------------------------------
// K4: GEMM support = x @ W (fp32 accum, bf16 out). Proven R3/R5 kernel.
// ---------------------------------------------------------------------------
#define XS_STRIDE 66

__global__ void __launch_bounds__(256, 2)
k_gemm(const float* __restrict__ x, const float* __restrict__ W) {
    extern __shared__ float sm[];
    float* Ws  = sm;
    float* xsT = sm + DH * DH;

    int tid  = threadIdx.x;
    int ty   = tid >> 5;
    int lane = tid & 31;

    for (int i = tid; i < DH * DH / 4; i += 256)
        ((float4*)Ws)[i] = ((const float4*)W)[i];

    int row0 = blockIdx.x * 64;
    {
        int d  = tid & 127;
        int rh = tid >> 7;
        #pragma unroll 8
        for (int rr = 0; rr < 32; rr++) {
            int r = rr * 2 + rh;
            int row = row0 + r;
            float v = (row < TOTROWS) ? x[(size_t)row * DH + d] : 0.f;
            xsT[d * XS_STRIDE + r] = v;
        }
    }
    __syncthreads();

    ull acc[4][4];
    #pragma unroll
    for (int rp = 0; rp < 4; rp++)
        #pragma unroll
        for (int c = 0; c < 4; c++) acc[rp][c] = 0ull;

    #pragma unroll 4
    for (int d = 0; d < DH; d++) {
        float4 w4 = *(const float4*)(Ws + d * DH + 4 * lane);
        ull ww0 = pack2(w4.x, w4.x);
        ull ww1 = pack2(w4.y, w4.y);
        ull ww2 = pack2(w4.z, w4.z);
        ull ww3 = pack2(w4.w, w4.w);
        const ull* xp = (const ull*)(xsT + d * XS_STRIDE + ty * 8);
        ull x0 = xp[0], x1 = xp[1], x2 = xp[2], x3 = xp[3];
        ffma2(acc[0][0], x0, ww0); ffma2(acc[0][1], x0, ww1);
        ffma2(acc[0][2], x0, ww2); ffma2(acc[0][3], x0, ww3);
        ffma2(acc[1][0], x1, ww0); ffma2(acc[1][1], x1, ww1);
        ffma2(acc[1][2], x1, ww2); ffma2(acc[1][3], x1, ww3);
        ffma2(acc[2][0], x2, ww0); ffma2(acc[2][1], x2, ww1);
        ffma2(acc[2][2], x2, ww2); ffma2(acc[2][3], x2, ww3);
        ffma2(acc[3][0], x3, ww0); ffma2(acc[3][1], x3, ww1);
        ffma2(acc[3][2], x3, ww2); ffma2(acc[3][3], x3, ww3);
    }

    #pragma unroll
    for (int rp = 0; rp < 4; rp++) {
        float lo0, hi0, lo1, hi1, lo2, hi2, lo3, hi3;
        unpack2(acc[rp][0], lo0, hi0);
        unpack2(acc[rp][1], lo1, hi1);
        unpack2(acc[rp][2], lo2, hi2);
        unpack2(acc[rp][3], lo3, hi3);
        int r = row0 + ty * 8 + 2 * rp;
        if (r < TOTROWS) {
            uint2 v = make_uint2(pack_bf16(lo0, lo1), pack_bf16(lo2, lo3));
            *(uint2*)(g_support + (size_t)r * 64 + 2 * lane) = v;
        }
        if (r + 1 < TOTROWS) {
            uint2 v = make_uint2(pack_bf16(hi0, hi1), pack_bf16(hi2, hi3));
            *(uint2*)(g_support + (size_t)(r + 1) * 64 + 2 * lane) = v;
        }
    }
}

// ---------------------------------------------------------------------------
// K5: gather + bias + GELU -> g_h (bf16). One warp per node, both batches.
// Edge loop unrolled x4 with batched independent loads (latency hiding).
// ---------------------------------------------------------------------------
#define GATHER_BLKS 1184

__global__ void __launch_bounds__(256, 4)
k_gather(const float* __restrict__ b) {
    __shared__ float bs[128];
    int tid = threadIdx.x;
    if (tid < 128) bs[tid] = b[tid];
    __syncthreads();

    int w    = tid >> 5;
    int lane = tid & 31;
    float4 bb = ((const float4*)bs)[lane];

    const uint2* sup = (const uint2*)g_support;
    int gw = blockIdx.x * 8 + w;

    for (int node = gw; node < NNODES; node += GATHER_BLKS * 8) {
        int beg = g_off[node];
        int end = g_off[node + 1];

        float4 a0 = make_float4(0.f, 0.f, 0.f, 0.f);
        float4 a1 = make_float4(0.f, 0.f, 0.f, 0.f);

        int j = beg;
        for (; j + 4 <= end; j += 4) {
            int s0 = __ldg(&g_adj[j]);
            int s1 = __ldg(&g_adj[j + 1]);
            int s2 = __ldg(&g_adj[j + 2]);
            int s3 = __ldg(&g_adj[j + 3]);
            uint2 p0 = __ldg(sup + (size_t)s0 * 32 + lane);
            uint2 p1 = __ldg(sup + (size_t)s1 * 32 + lane);
            uint2 p2 = __ldg(sup + (size_t)s2 * 32 + lane);
            uint2 p3 = __ldg(sup + (size_t)s3 * 32 + lane);
            uint2 q0 = __ldg(sup + ((size_t)NNODES + s0) * 32 + lane);
            uint2 q1 = __ldg(sup + ((size_t)NNODES + s1) * 32 + lane);
            uint2 q2 = __ldg(sup + ((size_t)NNODES + s2) * 32 + lane);
            uint2 q3 = __ldg(sup + ((size_t)NNODES + s3) * 32 + lane);
            a0.x += bf_lo(p0.x) + bf_lo(p1.x) + bf_lo(p2.x) + bf_lo(p3.x);
            a0.y += bf_hi(p0.x) + bf_hi(p1.x) + bf_hi(p2.x) + bf_hi(p3.x);
            a0.z += bf_lo(p0.y) + bf_lo(p1.y) + bf_lo(p2.y) + bf_lo(p3.y);
            a0.w += bf_hi(p0.y) + bf_hi(p1.y) + bf_hi(p2.y) + bf_hi(p3.y);
            a1.x += bf_lo(q0.x) + bf_lo(q1.x) + bf_lo(q2.x) + bf_lo(q3.x);
            a1.y += bf_hi(q0.x) + bf_hi(q1.x) + bf_hi(q2.x) + bf_hi(q3.x);
            a1.z += bf_lo(q0.y) + bf_lo(q1.y) + bf_lo(q2.y) + bf_lo(q3.y);
            a1.w += bf_hi(q0.y) + bf_hi(q1.y) + bf_hi(q2.y) + bf_hi(q3.y);
        }
        for (; j < end; j++) {
            int s0 = __ldg(&g_adj[j]);
            uint2 p0 = __ldg(sup + (size_t)s0 * 32 + lane);
            uint2 q0 = __ldg(sup + ((size_t)NNODES + s0) * 32 + lane);
            a0.x += bf_lo(p0.x); a0.y += bf_hi(p0.x);
            a0.z += bf_lo(p0.y); a0.w += bf_hi(p0.y);
            a1.x += bf_lo(q0.x); a1.y += bf_hi(q0.x);
            a1.z += bf_lo(q0.y); a1.w += bf_hi(q0.y);
        }

        float g0 = gelu_exact(a0.x + bb.x), g1 = gelu_exact(a0.y + bb.y);
        float g2 = gelu_exact(a0.z + bb.z), g3 = gelu_exact(a0.w + bb.w);
        ((uint2*)g_h)[(size_t)node * 32 + lane] =
            make_uint2(pack_bf16(g0, g1), pack_bf16(g2, g3));
        g0 = gelu_exact(a1.x + bb.x); g1 = gelu_exact(a1.y + bb.y);
        g2 = gelu_exact(a1.z + bb.z); g3 = gelu_exact(a1.w + bb.w);
        ((uint2*)g_h)[((size_t)NNODES + node) * 32 + lane] =
            make_uint2(pack_bf16(g0, g1), pack_bf16(g2, g3));
    }
}

// ---------------------------------------------------------------------------
// K6: batched MLP. Tile = 128 rows. Layer1 (128x64x128) + Layer2 (128x32x64)
// as register-tiled FFMA2 GEMMs; layer3 folded out by linearity of mean:
// accumulate per-batch column sums of h2; last block applies W3/b3.
// ---------------------------------------------------------------------------
#define ST 130
#define MLP_TILES ((HROWS) / 128)   // 782

__global__ void __launch_bounds__(256, 2)
k_mlp(const float* __restrict__ W1, const float* __restrict__ b1,
      const float* __restrict__ W2, const float* __restrict__ b2,
      const float* __restrict__ W3, const float* __restrict__ b3,
      float* __restrict__ out) {
    extern __shared__ float sm[];
    float* hsT  = sm;                    // [128 d][ST] (reused as h1sT [64][ST])
    float* W1s  = sm + 128 * ST;         // 8192  [128 d][64]
    float* W2s  = W1s + 8192;            // 2048  [64 d][32]
    float* b1s  = W2s + 2048;            // 64
    float* b2s  = b1s + 64;              // 32
    float* accs = b2s + 32;              // 64

    int tid = threadIdx.x;
    for (int i = tid; i < 8192; i += 256) W1s[i] = W1[i];
    for (int i = tid; i < 2048; i += 256) W2s[i] = W2[i];
    if (tid < 64) b1s[tid] = b1[tid];
    if (tid < 32) b2s[tid] = b2[tid];
    if (tid < 64) accs[tid] = 0.f;

    // stage h tile transposed: hsT[d][r] = h[row0+r][d]
    int row0 = blockIdx.x * 128;
    const uint2* hrow = (const uint2*)g_h;
    #pragma unroll 4
    for (int it = 0; it < 16; it++) {
        int idx = it * 256 + tid;     // 0..4095
        int r = idx >> 5;             // row in tile
        int c = idx & 31;             // uint2 col (4 d's)
        uint2 u = __ldg(hrow + (size_t)(row0 + r) * 32 + c);
        hsT[(4 * c + 0) * ST + r] = bf_lo(u.x);
        hsT[(4 * c + 1) * ST + r] = bf_hi(u.x);
        hsT[(4 * c + 2) * ST + r] = bf_lo(u.y);
        hsT[(4 * c + 3) * ST + r] = bf_hi(u.y);
    }
    __syncthreads();

    // ---- layer1: 128 rows x 64 cols, K=128. thread = 8 rows x 4 cols ----
    int colg = tid & 15;   // cols 4*colg..+3
    int rowg = tid >> 4;   // rows 8*rowg..+7

    ull acc[4][4];
    #pragma unroll
    for (int c = 0; c < 4; c++) {
        float bv = b1s[4 * colg + c];
        ull bp = pack2(bv, bv);
        #pragma unroll
        for (int rp = 0; rp < 4; rp++) acc[rp][c] = bp;
    }

    #pragma unroll 4
    for (int d = 0; d < 128; d++) {
        float4 w4 = *(const float4*)(W1s + d * 64 + 4 * colg);
        ull ww0 = pack2(w4.x, w4.x);
        ull ww1 = pack2(w4.y, w4.y);
        ull ww2 = pack2(w4.z, w4.z);
        ull ww3 = pack2(w4.w, w4.w);
        const ull* xp = (const ull*)(hsT + d * ST + rowg * 8);
        ull x0 = xp[0], x1 = xp[1], x2 = xp[2], x3 = xp[3];
        ffma2(acc[0][0], x0, ww0); ffma2(acc[0][1], x0, ww1);
        ffma2(acc[0][2], x0, ww2); ffma2(acc[0][3], x0, ww3);
        ffma2(acc[1][0], x1, ww0); ffma2(acc[1][1], x1, ww1);
        ffma2(acc[1][2], x1, ww2); ffma2(acc[1][3], x1, ww3);
        ffma2(acc[2][0], x2, ww0); ffma2(acc[2][1], x2, ww1);
        ffma2(acc[2][2], x2, ww2); ffma2(acc[2][3], x2, ww3);
        ffma2(acc[3][0], x3, ww0); ffma2(acc[3][1], x3, ww1);
        ffma2(acc[3][2], x3, ww2); ffma2(acc[3][3], x3, ww3);
    }
    __syncthreads();   // hsT reads done; safe to overwrite with h1sT

    // relu + write h1 transposed: h1sT[d2][r], d2 = 4*colg..+3
    float* h1sT = hsT;
    #pragma unroll
    for (int c = 0; c < 4; c++) {
        #pragma unroll
        for (int rp = 0; rp < 4; rp++) {
            float lo, hi; unpack2(acc[rp][c], lo, hi);
            lo = fmaxf(lo, 0.f); hi = fmaxf(hi, 0.f);
            *(ull*)(h1sT + (4 * colg + c) * ST + rowg * 8 + 2 * rp) = pack2(lo, hi);
        }
    }
    __syncthreads();

    // ---- layer2: 128 rows x 32 cols, K=64. thread = 8 rows x 2 cols ----
    ull acc2[4][2];
    #pragma unroll
    for (int c = 0; c < 2; c++) {
        float bv = b2s[2 * colg + c];
        ull bp = pack2(bv, bv);
        #pragma unroll
        for (int rp = 0; rp < 4; rp++) acc2[rp][c] = bp;
    }

    #pragma unroll 4
    for (int d = 0; d < 64; d++) {
        float2 w2 = *(const float2*)(W2s + d * 32 + 2 * colg);
        ull ww0 = pack2(w2.x, w2.x);
        ull ww1 = pack2(w2.y, w2.y);
        const ull* xp = (const ull*)(h1sT + d * ST + rowg * 8);
        ull x0 = xp[0], x1 = xp[1], x2 = xp[2], x3 = xp[3];
        ffma2(acc2[0][0], x0, ww0); ffma2(acc2[0][1], x0, ww1);
        ffma2(acc2[1][0], x1, ww0); ffma2(acc2[1][1], x1, ww1);
        ffma2(acc2[2][0], x2, ww0); ffma2(acc2[2][1], x2, ww1);
        ffma2(acc2[3][0], x3, ww0); ffma2(acc2[3][1], x3, ww1);
    }

    // relu + per-batch column sums of h2 (guard padded/out-of-range rows)
    #pragma unroll
    for (int c = 0; c < 2; c++) {
        float s0 = 0.f, s1 = 0.f;
        #pragma unroll
        for (int rp = 0; rp < 4; rp++) {
            float lo, hi; unpack2(acc2[rp][c], lo, hi);
            lo = fmaxf(lo, 0.f); hi = fmaxf(hi, 0.f);
            int r = row0 + rowg * 8 + 2 * rp;
            if (r < NNODES)            s0 += lo;
            else if (r < TOTROWS)      s1 += lo;
            if (r + 1 < NNODES)        s0 += hi;
            else if (r + 1 < TOTROWS)  s1 += hi;
        }
        atomicAdd(&accs[2 * colg + c],      s0);
        atomicAdd(&accs[32 + 2 * colg + c], s1);
    }
    __syncthreads();
    if (tid < 64) atomicAdd(&g_acc2[tid], accs[tid]);
    __threadfence();
    __syncthreads();

    // last block applies layer3 to the mean of h2
    if (tid == 0) {
        unsigned int prev = atomicAdd(&g_done, 1u);
        if (prev == (unsigned int)(gridDim.x - 1)) {
            #pragma unroll
            for (int o = 0; o < 10; o++) {
                float r0 = b3[o], r1 = b3[o];
                for (int c = 0; c < 32; c++) {
                    float w = W3[c * 10 + o];
                    r0 = fmaf(__ldcg(&g_acc2[c])      * (1.0f / NNODES), w, r0);
                    r1 = fmaf(__ldcg(&g_acc2[32 + c]) * (1.0f / NNODES), w, r1);
                }
                out[o]      = r0;
                out[10 + o] = r1;
            }
        }
    }
}

// ---------------------------------------------------------------------------
extern "C" void kernel_launch(void* const* d_in, const int* in_sizes, int n_in,
                              void* d_out, int out_size) {
    const float* x  = (const float*)d_in[0];
    const int*   ei = (const int*)  d_in[1];
    const float* W  = (const float*)d_in[2];
    const float* b  = (const float*)d_in[3];
    const float* W1 = (const float*)d_in[4];
    const float* b1 = (const float*)d_in[5];
    const float* W2 = (const float*)d_in[6];
    const float* b2 = (const float*)d_in[7];
    const float* W3 = (const float*)d_in[8];
    const float* b3 = (const float*)d_in[9];
    float* out = (float*)d_out;

    int nedges = in_sizes[1] / 2;

    const int GEMM_SMEM = (DH * DH + DH * XS_STRIDE) * (int)sizeof(float);        // 99328
    const int MLP_SMEM  = (128 * ST + 8192 + 2048 + 64 + 32 + 64) * (int)sizeof(float); // 108160

    cudaFuncSetAttribute(k_gemm, cudaFuncAttributeMaxDynamicSharedMemorySize, GEMM_SMEM);
    cudaFuncSetAttribute(k_mlp,  cudaFuncAttributeMaxDynamicSharedMemorySize, MLP_SMEM);

    k_zero  <<<98, 512>>>();
    k_hist  <<<1024, 256>>>(ei, nedges);
    k_prefix<<<1, 1024>>>();
    k_fill  <<<1024, 256>>>(ei, nedges);
    k_gemm  <<<(TOTROWS + 63) / 64, 256, GEMM_SMEM>>>(x, W);
    k_gather<<<GATHER_BLKS, 256>>>(b);
    k_mlp   <<<MLP_TILES, 256, MLP_SMEM>>>(W1, b1, W2, b2, W3, b3, out);
}